// round 9
// baseline (speedup 1.0000x reference)
#include <cuda_runtime.h>
#include <cuda_fp16.h>
#include <cstdint>
#include <cstddef>

// y = x @ (W + 2*A@B)^T + b ; x:[8192,4096] W:[4096,4096] r=16 (fp32 in/out)
// Single-pass fp16 mma.sync GEMM. X->fp16 conversion fused into the A-load
// path (LDG fp32 -> cvt -> STS). Register-level fragment double buffering:
// every ldmatrix batch issues one half-iteration ahead of its MMAs, so no
// MMA waits on shared-memory latency in steady state. rel_err ~2.9e-4.

#define M_TOT 8192
#define N_TOT 4096
#define K_TOT 4096
#define LORA_R 16

__device__ __align__(128) __half g_Wh[(size_t)N_TOT * K_TOT];  // 32 MB

// ---------------------------------------------------------------------------
__device__ __forceinline__ uint32_t smem_u32(const void* p) {
    uint32_t a;
    asm("{ .reg .u64 t; cvta.to.shared.u64 t, %1; cvt.u32.u64 %0, t; }"
        : "=r"(a) : "l"(p));
    return a;
}
__device__ __forceinline__ void cp_async16(uint32_t dst, const void* src) {
    asm volatile("cp.async.cg.shared.global [%0], [%1], 16;"
                 :: "r"(dst), "l"(src) : "memory");
}
__device__ __forceinline__ void sts128(uint32_t addr, uint32_t r0, uint32_t r1,
                                       uint32_t r2, uint32_t r3) {
    asm volatile("st.shared.v4.b32 [%0], {%1,%2,%3,%4};"
                 :: "r"(addr), "r"(r0), "r"(r1), "r"(r2), "r"(r3) : "memory");
}
__device__ __forceinline__ void ldsm_x4(uint32_t (&r)[4], uint32_t addr) {
    asm volatile("ldmatrix.sync.aligned.m8n8.x4.shared.b16 {%0,%1,%2,%3}, [%4];"
                 : "=r"(r[0]), "=r"(r[1]), "=r"(r[2]), "=r"(r[3]) : "r"(addr));
}
__device__ __forceinline__ void mma16816(float (&d)[4], const uint32_t (&a)[4],
                                         uint32_t b0, uint32_t b1) {
    asm volatile(
        "mma.sync.aligned.m16n8k16.row.col.f32.f16.f16.f32 "
        "{%0,%1,%2,%3}, {%4,%5,%6,%7}, {%8,%9}, {%0,%1,%2,%3};"
        : "+f"(d[0]), "+f"(d[1]), "+f"(d[2]), "+f"(d[3])
        : "r"(a[0]), "r"(a[1]), "r"(a[2]), "r"(a[3]), "r"(b0), "r"(b1));
}
__device__ __forceinline__ uint32_t pack_h2(float x, float y) {
    __half2 h = __floats2half2_rn(x, y);
    return *reinterpret_cast<uint32_t*>(&h);
}

// ---------------------------------------------------------------------------
// Fold LoRA into W and round to fp16 (once; W reused by 64 M-tiles).
// ---------------------------------------------------------------------------
__global__ __launch_bounds__(256)
void fold_w_kernel(const float* __restrict__ W,
                   const float* __restrict__ A,    // [N, R]
                   const float* __restrict__ B) {  // [R, K]
    __shared__ float a_sh[LORA_R];
    const int o = blockIdx.y;
    if (threadIdx.x < LORA_R)
        a_sh[threadIdx.x] = A[(size_t)o * LORA_R + threadIdx.x];
    __syncthreads();

    const int i4 = blockIdx.x * 256 + threadIdx.x;
    float4 w = reinterpret_cast<const float4*>(W + (size_t)o * K_TOT)[i4];
    float4 acc = make_float4(0.f, 0.f, 0.f, 0.f);
#pragma unroll
    for (int r = 0; r < LORA_R; r++) {
        const float4 bv = reinterpret_cast<const float4*>(B + (size_t)r * K_TOT)[i4];
        const float a = a_sh[r];
        acc.x += a * bv.x; acc.y += a * bv.y; acc.z += a * bv.z; acc.w += a * bv.w;
    }
    __half2* p = reinterpret_cast<__half2*>(g_Wh + (size_t)o * K_TOT) + 2 * i4;
    p[0] = __floats2half2_rn(w.x + 2.f * acc.x, w.y + 2.f * acc.y);
    p[1] = __floats2half2_rn(w.z + 2.f * acc.z, w.w + 2.f * acc.w);
}

// ---------------------------------------------------------------------------
// GEMM: 128x128 CTA tile, BK=32, 4 warps (2x2), warp tile 64x64, 4 stages,
// fragment double-buffered mainloop (no exposed ldmatrix latency).
// SMEM rows padded to 80B: ldmatrix conflict-free (row stride 20 banks).
// ---------------------------------------------------------------------------
#define BM 128
#define BN 128
#define BK 32
#define ROW_B 80
#define TILE_B (128 * ROW_B)           // 10240 per operand
#define STAGE_B (2 * TILE_B)           // 20480
#define SMEM_TOTAL (4 * STAGE_B)       // 81920
#define ITERS (K_TOT / BK)             // 128

__global__ __launch_bounds__(128, 2)
void gemm_mma_kernel(const float* __restrict__ X,
                     const float* __restrict__ bias, float* __restrict__ Y) {
    extern __shared__ __align__(128) char smem[];
    const uint32_t sb = smem_u32(smem);
    const int tid = threadIdx.x;
    const int lid = tid & 31;
    const int wid = tid >> 5;
    const int wm = (wid & 1) * 64;
    const int wn = (wid >> 1) * 64;

    const size_t bm = (size_t)blockIdx.y * BM;
    const size_t bn = (size_t)blockIdx.x * BN;

    // Per-thread tile geometry: 4 chunks of 8 K-elements.
    uint32_t soff[4];
    size_t gA[4], gB[4];
#pragma unroll
    for (int t = 0; t < 4; t++) {
        const int f = tid + t * 128;
        const int row = f >> 2;
        const int c = f & 3;
        soff[t] = (uint32_t)(row * ROW_B + c * 16);
        gA[t] = (bm + row) * (size_t)K_TOT + c * 8;
        gB[t] = (bn + row) * (size_t)K_TOT + c * 8;
    }

    // A path: LDG fp32 -> cvt fp16 immediately (16 packed regs held).
    uint32_t ah[16];
    auto ldg_cvt_a = [&](int j) {
        const size_t k0 = (size_t)j << 5;
#pragma unroll
        for (int t = 0; t < 4; t++) {
            const float4 v0 = *reinterpret_cast<const float4*>(X + k0 + gA[t]);
            const float4 v1 = *reinterpret_cast<const float4*>(X + k0 + gA[t] + 4);
            ah[4 * t + 0] = pack_h2(v0.x, v0.y);
            ah[4 * t + 1] = pack_h2(v0.z, v0.w);
            ah[4 * t + 2] = pack_h2(v1.x, v1.y);
            ah[4 * t + 3] = pack_h2(v1.z, v1.w);
        }
    };
    auto sts_a = [&](int s) {
        const uint32_t aB = sb + (uint32_t)s * STAGE_B;
#pragma unroll
        for (int t = 0; t < 4; t++)
            sts128(aB + soff[t], ah[4 * t], ah[4 * t + 1], ah[4 * t + 2], ah[4 * t + 3]);
    };
    auto load_b = [&](int s, int j) {
        if (j < ITERS) {
            const size_t k0 = (size_t)j << 5;
            const uint32_t bB = sb + (uint32_t)s * STAGE_B + TILE_B;
#pragma unroll
            for (int t = 0; t < 4; t++)
                cp_async16(bB + soff[t], g_Wh + k0 + gB[t]);
        }
        asm volatile("cp.async.commit_group;" ::: "memory");
    };

    float acc[4][8][4];
#pragma unroll
    for (int i = 0; i < 4; i++)
#pragma unroll
        for (int j = 0; j < 8; j++)
#pragma unroll
            for (int q = 0; q < 4; q++) acc[i][j][q] = 0.f;

    const int lrow = lid & 15;
    const int lkh = lid >> 4;

    // Fragment buffers (double-buffered).
    uint32_t aF0[4][4], bF0[4][4], aF1[4][4], bF1[4][4];

    auto ld_frags = [&](int s, int kc, uint32_t (&a)[4][4], uint32_t (&br)[4][4]) {
        const uint32_t aB = sb + (uint32_t)s * STAGE_B;
        const uint32_t bB = aB + TILE_B;
        const uint32_t koff = (uint32_t)((kc * 16 + lkh * 8) * 2);
#pragma unroll
        for (int mg = 0; mg < 4; mg++)
            ldsm_x4(a[mg], aB + (uint32_t)((wm + mg * 16 + lrow) * ROW_B) + koff);
#pragma unroll
        for (int np = 0; np < 4; np++)
            ldsm_x4(br[np], bB + (uint32_t)((wn + np * 16 + lrow) * ROW_B) + koff);
    };
    auto do_mma = [&](uint32_t (&a)[4][4], uint32_t (&br)[4][4]) {
#pragma unroll
        for (int mg = 0; mg < 4; mg++)
#pragma unroll
            for (int ng = 0; ng < 8; ng++)
                mma16816(acc[mg][ng], a[mg],
                         br[ng >> 1][ng & 1], br[ng >> 1][(ng & 1) + 2]);
    };

    // Prologue: fill stages 0..2; prime ah with j=3; prefetch kc0 frags.
#pragma unroll
    for (int j = 0; j < 3; j++) {
        ldg_cvt_a(j);
        sts_a(j);
        load_b(j, j);
    }
    ldg_cvt_a(3);
    asm volatile("cp.async.wait_group %0;" :: "n"(1) : "memory");  // groups 0,1 done
    __syncthreads();
    ld_frags(0, 0, aF0, bF0);

    for (int i = 0; i < ITERS; i++) {
        const int s = i & 3;

        // kc1 fragments for this stage (data: group i, drained at iter i-1).
        ld_frags(s, 1, aF1, bF1);
        // kc0 MMAs hide the kc1 ldmatrix latency.
        do_mma(aF0, bF0);

        // group i+1 done (for next-stage kc0 prefetch below).
        asm volatile("cp.async.wait_group %0;" :: "n"(1) : "memory");
        // Separate iter i-1's reads of stage (i-1)&3 from its refill below.
        __syncthreads();

        // Refill stage (i+3)&3 == (i-1)&3 with data for iter i+3.
        if (i + 3 < ITERS) sts_a((i + 3) & 3);
        load_b((i + 3) & 3, i + 3);
        if (i + 4 < ITERS) ldg_cvt_a(i + 4);

        // Next-stage kc0 fragments; hidden behind kc1 MMAs.
        if (i + 1 < ITERS) ld_frags((i + 1) & 3, 0, aF0, bF0);
        do_mma(aF1, bF1);
    }

    // Epilogue: add bias, float2 stores.
#pragma unroll
    for (int ng = 0; ng < 8; ng++) {
        const size_t c = bn + wn + ng * 8 + (lid & 3) * 2;
        const float2 bv = *reinterpret_cast<const float2*>(bias + c);
#pragma unroll
        for (int mg = 0; mg < 4; mg++) {
            const size_t r = bm + wm + mg * 16 + (lid >> 2);
            float2 o0, o1;
            o0.x = acc[mg][ng][0] + bv.x;
            o0.y = acc[mg][ng][1] + bv.y;
            o1.x = acc[mg][ng][2] + bv.x;
            o1.y = acc[mg][ng][3] + bv.y;
            *reinterpret_cast<float2*>(Y + r * N_TOT + c) = o0;
            *reinterpret_cast<float2*>(Y + (r + 8) * N_TOT + c) = o1;
        }
    }
}

// ---------------------------------------------------------------------------
extern "C" void kernel_launch(void* const* d_in, const int* in_sizes, int n_in,
                              void* d_out, int out_size) {
    const float* x  = (const float*)d_in[0];
    const float* W  = (const float*)d_in[1];
    const float* b  = (const float*)d_in[2];
    const float* lA = (const float*)d_in[3];
    const float* lB = (const float*)d_in[4];
    float* y = (float*)d_out;

    fold_w_kernel<<<dim3(K_TOT / 1024, N_TOT), 256>>>(W, lA, lB);

    cudaFuncSetAttribute(gemm_mma_kernel,
                         cudaFuncAttributeMaxDynamicSharedMemorySize, SMEM_TOTAL);
    dim3 grid(N_TOT / BN, M_TOT / BM);  // (32, 64) — n-fastest raster
    gemm_mma_kernel<<<grid, 128, SMEM_TOTAL>>>(x, b, y);
}

// round 10
// speedup vs baseline: 1.3340x; 1.3340x over previous
#include <cuda_runtime.h>
#include <cuda_fp16.h>
#include <cstdint>
#include <cstddef>

// y = x @ (W + 2*A@B)^T + b ; x:[8192,4096] W:[4096,4096] r=16 (fp32 in/out)
// Single-pass fp16 mma.sync GEMM (X, Weff pre-rounded to fp16; rel_err 2.9e-4).
// 256 threads, 8 warps (2x4), warp tile 64x32 (acc=64 regs), 4-stage cp.async
// smem pipeline + register fragment double-buffering (no exposed LDSM latency),
// __launch_bounds__(256,2) to pin regs <=128 -> 16 warps/SM.

#define M_TOT 8192
#define N_TOT 4096
#define K_TOT 4096
#define LORA_R 16

__device__ __align__(128) __half g_Xh[(size_t)M_TOT * K_TOT];  // 64 MB
__device__ __align__(128) __half g_Wh[(size_t)N_TOT * K_TOT];  // 32 MB

// ---------------------------------------------------------------------------
__device__ __forceinline__ uint32_t smem_u32(const void* p) {
    uint32_t a;
    asm("{ .reg .u64 t; cvta.to.shared.u64 t, %1; cvt.u32.u64 %0, t; }"
        : "=r"(a) : "l"(p));
    return a;
}
__device__ __forceinline__ void cp_async16(uint32_t dst, const void* src) {
    asm volatile("cp.async.cg.shared.global [%0], [%1], 16;"
                 :: "r"(dst), "l"(src) : "memory");
}
__device__ __forceinline__ void ldsm_x4(uint32_t (&r)[4], uint32_t addr) {
    asm volatile("ldmatrix.sync.aligned.m8n8.x4.shared.b16 {%0,%1,%2,%3}, [%4];"
                 : "=r"(r[0]), "=r"(r[1]), "=r"(r[2]), "=r"(r[3]) : "r"(addr));
}
__device__ __forceinline__ void mma16816(float (&d)[4], const uint32_t (&a)[4],
                                         uint32_t b0, uint32_t b1) {
    asm volatile(
        "mma.sync.aligned.m16n8k16.row.col.f32.f16.f16.f32 "
        "{%0,%1,%2,%3}, {%4,%5,%6,%7}, {%8,%9}, {%0,%1,%2,%3};"
        : "+f"(d[0]), "+f"(d[1]), "+f"(d[2]), "+f"(d[3])
        : "r"(a[0]), "r"(a[1]), "r"(a[2]), "r"(a[3]), "r"(b0), "r"(b1));
}

// ---------------------------------------------------------------------------
// Prep kernels
// ---------------------------------------------------------------------------
__global__ __launch_bounds__(256)
void conv_x_kernel(const float* __restrict__ X) {
    const size_t i = (size_t)blockIdx.x * 256 + threadIdx.x;  // float4 index
    const float4 v = reinterpret_cast<const float4*>(X)[i];
    __half2* p = reinterpret_cast<__half2*>(g_Xh) + 2 * i;
    p[0] = __floats2half2_rn(v.x, v.y);
    p[1] = __floats2half2_rn(v.z, v.w);
}

__global__ __launch_bounds__(256)
void fold_w_kernel(const float* __restrict__ W,
                   const float* __restrict__ A,    // [N, R]
                   const float* __restrict__ B) {  // [R, K]
    __shared__ float a_sh[LORA_R];
    const int o = blockIdx.y;
    if (threadIdx.x < LORA_R)
        a_sh[threadIdx.x] = A[(size_t)o * LORA_R + threadIdx.x];
    __syncthreads();

    const int i4 = blockIdx.x * 256 + threadIdx.x;
    float4 w = reinterpret_cast<const float4*>(W + (size_t)o * K_TOT)[i4];
    float4 acc = make_float4(0.f, 0.f, 0.f, 0.f);
#pragma unroll
    for (int r = 0; r < LORA_R; r++) {
        const float4 bv = reinterpret_cast<const float4*>(B + (size_t)r * K_TOT)[i4];
        const float a = a_sh[r];
        acc.x += a * bv.x; acc.y += a * bv.y; acc.z += a * bv.z; acc.w += a * bv.w;
    }
    __half2* p = reinterpret_cast<__half2*>(g_Wh + (size_t)o * K_TOT) + 2 * i4;
    p[0] = __floats2half2_rn(w.x + 2.f * acc.x, w.y + 2.f * acc.y);
    p[1] = __floats2half2_rn(w.z + 2.f * acc.z, w.w + 2.f * acc.w);
}

// ---------------------------------------------------------------------------
// GEMM: 128x128 CTA tile, BK=32, 8 warps (2m x 4n), warp tile 64x32,
// 4 smem stages, fragment double-buffered mainloop.
// SMEM rows padded to 80B: ldmatrix conflict-free (row stride 20 banks).
// ---------------------------------------------------------------------------
#define BM 128
#define BN 128
#define BK 32
#define ROW_B 80
#define TILE_B (128 * ROW_B)           // 10240 per operand
#define STAGE_B (2 * TILE_B)           // 20480
#define SMEM_TOTAL (4 * STAGE_B)       // 81920
#define ITERS (K_TOT / BK)             // 128

__global__ __launch_bounds__(256, 2)
void gemm_mma_kernel(const float* __restrict__ bias, float* __restrict__ Y) {
    extern __shared__ __align__(128) char smem[];
    const uint32_t sb = smem_u32(smem);
    const int tid = threadIdx.x;
    const int lid = tid & 31;
    const int wid = tid >> 5;
    const int wm = (wid & 1) * 64;     // warp M offset
    const int wn = (wid >> 1) * 32;    // warp N offset

    const size_t bm = (size_t)blockIdx.y * BM;
    const size_t bn = (size_t)blockIdx.x * BN;

    // Cooperative loads: per operand 512 x 16B chunks, 2 per thread.
    uint32_t soff[2], gA[2], gB[2];    // gA/gB: byte offsets (fit in u32)
#pragma unroll
    for (int t = 0; t < 2; t++) {
        const int f = tid + t * 256;
        const int row = f >> 2;
        const int c = f & 3;
        soff[t] = (uint32_t)(row * ROW_B + c * 16);
        gA[t] = (uint32_t)(((bm + row) * K_TOT + c * 8) * 2);
        gB[t] = (uint32_t)(((bn + row) * K_TOT + c * 8) * 2);
    }
    const char* Xb = reinterpret_cast<const char*>(g_Xh);
    const char* Wb = reinterpret_cast<const char*>(g_Wh);

    auto load_stage = [&](int s, int j) {
        if (j < ITERS) {
            const uint32_t k0 = (uint32_t)j * (BK * 2);  // byte offset in K
            const uint32_t aB = sb + (uint32_t)s * STAGE_B;
            const uint32_t bB = aB + TILE_B;
#pragma unroll
            for (int t = 0; t < 2; t++) {
                cp_async16(aB + soff[t], Xb + k0 + gA[t]);
                cp_async16(bB + soff[t], Wb + k0 + gB[t]);
            }
        }
        asm volatile("cp.async.commit_group;" ::: "memory");
    };

    float acc[4][4][4];
#pragma unroll
    for (int i = 0; i < 4; i++)
#pragma unroll
        for (int j = 0; j < 4; j++)
#pragma unroll
            for (int q = 0; q < 4; q++) acc[i][j][q] = 0.f;

    const int lrow = lid & 15;
    const int lkh = lid >> 4;

    // Fragment double buffers.
    uint32_t aF0[4][4], bF0[2][4], aF1[4][4], bF1[2][4];

    auto ld_frags = [&](int s, int kc, uint32_t (&a)[4][4], uint32_t (&br)[2][4]) {
        const uint32_t aB = sb + (uint32_t)s * STAGE_B;
        const uint32_t bB = aB + TILE_B;
        const uint32_t koff = (uint32_t)((kc * 16 + lkh * 8) * 2);
#pragma unroll
        for (int mg = 0; mg < 4; mg++)
            ldsm_x4(a[mg], aB + (uint32_t)((wm + mg * 16 + lrow) * ROW_B) + koff);
#pragma unroll
        for (int np = 0; np < 2; np++)
            ldsm_x4(br[np], bB + (uint32_t)((wn + np * 16 + lrow) * ROW_B) + koff);
    };
    auto do_mma = [&](uint32_t (&a)[4][4], uint32_t (&br)[2][4]) {
#pragma unroll
        for (int mg = 0; mg < 4; mg++)
#pragma unroll
            for (int ng = 0; ng < 4; ng++)
                mma16816(acc[mg][ng], a[mg],
                         br[ng >> 1][ng & 1], br[ng >> 1][(ng & 1) + 2]);
    };

    // Prologue: commit stages 0..2; prefetch stage-0 kc0 fragments.
#pragma unroll
    for (int j = 0; j < 3; j++) load_stage(j, j);
    asm volatile("cp.async.wait_group %0;" :: "n"(1) : "memory");
    __syncthreads();
    ld_frags(0, 0, aF0, bF0);

    for (int i = 0; i < ITERS; i++) {
        const int s = i & 3;

        // kc1 fragments for this stage; latency hidden behind kc0 MMAs.
        ld_frags(s, 1, aF1, bF1);
        do_mma(aF0, bF0);

        // All threads' groups <= i+1 complete; make them CTA-visible and
        // fence stage (i-1)&3 reads from its refill below.
        asm volatile("cp.async.wait_group %0;" :: "n"(1) : "memory");
        __syncthreads();

        // Refill stage (i+3)&3 == (i-1)&3 with data for iter i+3.
        load_stage((i + 3) & 3, i + 3);

        // Next-stage kc0 fragments; hidden behind kc1 MMAs.
        if (i + 1 < ITERS) ld_frags((i + 1) & 3, 0, aF0, bF0);
        do_mma(aF1, bF1);
    }

    // Epilogue: add bias, float2 stores.
#pragma unroll
    for (int ng = 0; ng < 4; ng++) {
        const size_t c = bn + wn + ng * 8 + (lid & 3) * 2;
        const float2 bv = *reinterpret_cast<const float2*>(bias + c);
#pragma unroll
        for (int mg = 0; mg < 4; mg++) {
            const size_t r = bm + wm + mg * 16 + (lid >> 2);
            float2 o0, o1;
            o0.x = acc[mg][ng][0] + bv.x;
            o0.y = acc[mg][ng][1] + bv.y;
            o1.x = acc[mg][ng][2] + bv.x;
            o1.y = acc[mg][ng][3] + bv.y;
            *reinterpret_cast<float2*>(Y + r * N_TOT + c) = o0;
            *reinterpret_cast<float2*>(Y + (r + 8) * N_TOT + c) = o1;
        }
    }
}

// ---------------------------------------------------------------------------
extern "C" void kernel_launch(void* const* d_in, const int* in_sizes, int n_in,
                              void* d_out, int out_size) {
    const float* x  = (const float*)d_in[0];
    const float* W  = (const float*)d_in[1];
    const float* b  = (const float*)d_in[2];
    const float* lA = (const float*)d_in[3];
    const float* lB = (const float*)d_in[4];
    float* y = (float*)d_out;

    conv_x_kernel<<<(unsigned)((size_t)M_TOT * K_TOT / 4 / 256), 256>>>(x);
    fold_w_kernel<<<dim3(K_TOT / 1024, N_TOT), 256>>>(W, lA, lB);

    cudaFuncSetAttribute(gemm_mma_kernel,
                         cudaFuncAttributeMaxDynamicSharedMemorySize, SMEM_TOTAL);
    dim3 grid(N_TOT / BN, M_TOT / BM);  // (32, 64) — n-fastest raster
    gemm_mma_kernel<<<grid, 256, SMEM_TOTAL>>>(b, y);
}

// round 11
// speedup vs baseline: 1.5959x; 1.1964x over previous
#include <cuda_runtime.h>
#include <cuda_fp16.h>
#include <cstdint>
#include <cstddef>

// y = x @ (W + 2*A@B)^T + b ; x:[8192,4096] W:[4096,4096] r=16 (fp32 in/out)
// Single-pass fp16 mma.sync GEMM (X, Weff pre-rounded fp16; rel_err 2.9e-4).
// sm_103 legacy-HMMA floor: ~1 HMMA / 16 cyc / SMSP -> GEMM floor ~920 us.
// Config = best measured per-pass shape (R3): 256 threads, 8 warps (2m x 4n),
// warp tile 64x32, simple inline kc loop (ptxas-scheduled), 4-stage cp.async.
// Odd warps traverse kc in reverse order to decorrelate ldsm phases.

#define M_TOT 8192
#define N_TOT 4096
#define K_TOT 4096
#define LORA_R 16

__device__ __align__(128) __half g_Xh[(size_t)M_TOT * K_TOT];  // 64 MB
__device__ __align__(128) __half g_Wh[(size_t)N_TOT * K_TOT];  // 32 MB

// ---------------------------------------------------------------------------
__device__ __forceinline__ uint32_t smem_u32(const void* p) {
    uint32_t a;
    asm("{ .reg .u64 t; cvta.to.shared.u64 t, %1; cvt.u32.u64 %0, t; }"
        : "=r"(a) : "l"(p));
    return a;
}
__device__ __forceinline__ void cp_async16(uint32_t dst, const void* src) {
    asm volatile("cp.async.cg.shared.global [%0], [%1], 16;"
                 :: "r"(dst), "l"(src) : "memory");
}
__device__ __forceinline__ void ldsm_x4(uint32_t (&r)[4], uint32_t addr) {
    asm volatile("ldmatrix.sync.aligned.m8n8.x4.shared.b16 {%0,%1,%2,%3}, [%4];"
                 : "=r"(r[0]), "=r"(r[1]), "=r"(r[2]), "=r"(r[3]) : "r"(addr));
}
__device__ __forceinline__ void mma16816(float (&d)[4], const uint32_t (&a)[4],
                                         uint32_t b0, uint32_t b1) {
    asm volatile(
        "mma.sync.aligned.m16n8k16.row.col.f32.f16.f16.f32 "
        "{%0,%1,%2,%3}, {%4,%5,%6,%7}, {%8,%9}, {%0,%1,%2,%3};"
        : "+f"(d[0]), "+f"(d[1]), "+f"(d[2]), "+f"(d[3])
        : "r"(a[0]), "r"(a[1]), "r"(a[2]), "r"(a[3]), "r"(b0), "r"(b1));
}

// ---------------------------------------------------------------------------
// Prep kernels
// ---------------------------------------------------------------------------
__global__ __launch_bounds__(256)
void conv_x_kernel(const float* __restrict__ X) {
    const size_t i = (size_t)blockIdx.x * 256 + threadIdx.x;  // float4 index
    const float4 v = reinterpret_cast<const float4*>(X)[i];
    __half2* p = reinterpret_cast<__half2*>(g_Xh) + 2 * i;
    p[0] = __floats2half2_rn(v.x, v.y);
    p[1] = __floats2half2_rn(v.z, v.w);
}

__global__ __launch_bounds__(256)
void fold_w_kernel(const float* __restrict__ W,
                   const float* __restrict__ A,    // [N, R]
                   const float* __restrict__ B) {  // [R, K]
    __shared__ float a_sh[LORA_R];
    const int o = blockIdx.y;
    if (threadIdx.x < LORA_R)
        a_sh[threadIdx.x] = A[(size_t)o * LORA_R + threadIdx.x];
    __syncthreads();

    const int i4 = blockIdx.x * 256 + threadIdx.x;
    float4 w = reinterpret_cast<const float4*>(W + (size_t)o * K_TOT)[i4];
    float4 acc = make_float4(0.f, 0.f, 0.f, 0.f);
#pragma unroll
    for (int r = 0; r < LORA_R; r++) {
        const float4 bv = reinterpret_cast<const float4*>(B + (size_t)r * K_TOT)[i4];
        const float a = a_sh[r];
        acc.x += a * bv.x; acc.y += a * bv.y; acc.z += a * bv.z; acc.w += a * bv.w;
    }
    __half2* p = reinterpret_cast<__half2*>(g_Wh + (size_t)o * K_TOT) + 2 * i4;
    p[0] = __floats2half2_rn(w.x + 2.f * acc.x, w.y + 2.f * acc.y);
    p[1] = __floats2half2_rn(w.z + 2.f * acc.z, w.w + 2.f * acc.w);
}

// ---------------------------------------------------------------------------
// GEMM: 128x128 CTA tile, BK=32, 8 warps (2m x 4n), warp tile 64x32,
// 4 smem stages, simple inline kc loop.
// SMEM rows padded to 80B: ldmatrix conflict-free (row stride 20 banks).
// ---------------------------------------------------------------------------
#define BM 128
#define BN 128
#define BK 32
#define STAGES 4
#define ROW_B 80
#define TILE_B (128 * ROW_B)           // 10240 per operand
#define STAGE_B (2 * TILE_B)           // 20480
#define SMEM_TOTAL (STAGES * STAGE_B)  // 81920
#define ITERS (K_TOT / BK)             // 128

__global__ __launch_bounds__(256, 2)
void gemm_mma_kernel(const float* __restrict__ bias, float* __restrict__ Y) {
    extern __shared__ __align__(128) char smem[];
    const uint32_t sb = smem_u32(smem);
    const int tid = threadIdx.x;
    const int lid = tid & 31;
    const int wid = tid >> 5;
    const int wm = (wid & 1) * 64;     // warp M offset
    const int wn = (wid >> 1) * 32;    // warp N offset

    const size_t bm = (size_t)blockIdx.y * BM;
    const size_t bn = (size_t)blockIdx.x * BN;

    // Cooperative loads: per operand 512 x 16B chunks, 2 per thread.
    uint32_t soff[2], gA[2], gB[2];    // global offsets in bytes (fit u32)
#pragma unroll
    for (int t = 0; t < 2; t++) {
        const int f = tid + t * 256;
        const int row = f >> 2;
        const int c = f & 3;
        soff[t] = (uint32_t)(row * ROW_B + c * 16);
        gA[t] = (uint32_t)(((bm + row) * K_TOT + c * 8) * 2);
        gB[t] = (uint32_t)(((bn + row) * K_TOT + c * 8) * 2);
    }
    const char* Xb = reinterpret_cast<const char*>(g_Xh);
    const char* Wb = reinterpret_cast<const char*>(g_Wh);

    auto load_stage = [&](int s, int j) {
        if (j < ITERS) {
            const uint32_t k0 = (uint32_t)j * (BK * 2);
            const uint32_t aB = sb + (uint32_t)s * STAGE_B;
            const uint32_t bB = aB + TILE_B;
#pragma unroll
            for (int t = 0; t < 2; t++) {
                cp_async16(aB + soff[t], Xb + k0 + gA[t]);
                cp_async16(bB + soff[t], Wb + k0 + gB[t]);
            }
        }
        asm volatile("cp.async.commit_group;" ::: "memory");
    };

    float acc[4][4][4];
#pragma unroll
    for (int i = 0; i < 4; i++)
#pragma unroll
        for (int j = 0; j < 4; j++)
#pragma unroll
            for (int q = 0; q < 4; q++) acc[i][j][q] = 0.f;

    const int lrow = lid & 15;
    const int lkh = lid >> 4;
    const int kcflip = wid & 1;        // odd warps run kc in reverse order

#pragma unroll
    for (int s = 0; s < STAGES - 1; s++) load_stage(s, s);

    for (int i = 0; i < ITERS; i++) {
        asm volatile("cp.async.wait_group %0;" :: "n"(STAGES - 2) : "memory");
        __syncthreads();

        load_stage((i + STAGES - 1) & (STAGES - 1), i + STAGES - 1);

        const int s = i & (STAGES - 1);
        const uint32_t aB = sb + (uint32_t)s * STAGE_B;
        const uint32_t bB = aB + TILE_B;

#pragma unroll
        for (int kx = 0; kx < 2; kx++) {
            const int kc = kx ^ kcflip;
            const uint32_t koff = (uint32_t)((kc * 16 + lkh * 8) * 2);
            uint32_t a[4][4], br[2][4];
#pragma unroll
            for (int mg = 0; mg < 4; mg++)
                ldsm_x4(a[mg], aB + (uint32_t)((wm + mg * 16 + lrow) * ROW_B) + koff);
#pragma unroll
            for (int np = 0; np < 2; np++)
                ldsm_x4(br[np], bB + (uint32_t)((wn + np * 16 + lrow) * ROW_B) + koff);
#pragma unroll
            for (int mg = 0; mg < 4; mg++)
#pragma unroll
                for (int ng = 0; ng < 4; ng++)
                    mma16816(acc[mg][ng], a[mg],
                             br[ng >> 1][ng & 1], br[ng >> 1][(ng & 1) + 2]);
        }
    }

    // Epilogue: add bias, float2 stores.
#pragma unroll
    for (int ng = 0; ng < 4; ng++) {
        const size_t c = bn + wn + ng * 8 + (lid & 3) * 2;
        const float2 bv = *reinterpret_cast<const float2*>(bias + c);
#pragma unroll
        for (int mg = 0; mg < 4; mg++) {
            const size_t r = bm + wm + mg * 16 + (lid >> 2);
            float2 o0, o1;
            o0.x = acc[mg][ng][0] + bv.x;
            o0.y = acc[mg][ng][1] + bv.y;
            o1.x = acc[mg][ng][2] + bv.x;
            o1.y = acc[mg][ng][3] + bv.y;
            *reinterpret_cast<float2*>(Y + r * N_TOT + c) = o0;
            *reinterpret_cast<float2*>(Y + (r + 8) * N_TOT + c) = o1;
        }
    }
}

// ---------------------------------------------------------------------------
extern "C" void kernel_launch(void* const* d_in, const int* in_sizes, int n_in,
                              void* d_out, int out_size) {
    const float* x  = (const float*)d_in[0];
    const float* W  = (const float*)d_in[1];
    const float* b  = (const float*)d_in[2];
    const float* lA = (const float*)d_in[3];
    const float* lB = (const float*)d_in[4];
    float* y = (float*)d_out;

    conv_x_kernel<<<(unsigned)((size_t)M_TOT * K_TOT / 4 / 256), 256>>>(x);
    fold_w_kernel<<<dim3(K_TOT / 1024, N_TOT), 256>>>(W, lA, lB);

    cudaFuncSetAttribute(gemm_mma_kernel,
                         cudaFuncAttributeMaxDynamicSharedMemorySize, SMEM_TOTAL);
    dim3 grid(N_TOT / BN, M_TOT / BM);  // (32, 64) — n-fastest raster
    gemm_mma_kernel<<<grid, 256, SMEM_TOTAL>>>(b, y);
}